// round 14
// baseline (speedup 1.0000x reference)
#include <cuda_runtime.h>
#include <cuda_fp16.h>
#include <cstdint>
#include <math.h>

#define N_INST 256
#define BATCH  128
#define IN_DIM 1024
#define L_DIM  512

// ---------------- device scratch (allocation-free rule) ----------------
__device__ __align__(256) __half g_x[(size_t)N_INST * BATCH * IN_DIM]; // 64MB fp16
__device__ __align__(256) __half g_v[L_DIM * IN_DIM];  // [l][k] transposed, fp16
__device__ __align__(256) __half g_u[L_DIM * IN_DIM];
// transposed partials: [b][n*8 + chunk] for coalesced softmax reads
__device__ float g_part[BATCH * N_INST * 8];

// ---------------- helpers ----------------
__device__ __forceinline__ uint32_t smem_u32(const void* p) {
    uint32_t a;
    asm("{ .reg .u64 t; cvta.to.shared.u64 t, %1; cvt.u32.u64 %0, t; }" : "=r"(a) : "l"(p));
    return a;
}
// 128B-row swizzle (SW128): XOR row bits [9:7] into 16B-chunk bits [6:4]
#define SWZ128(off) ((off) ^ (((off) >> 3) & 0x70))

#define CP16(dst, src) \
    asm volatile("cp.async.cg.shared.global [%0], [%1], 16;" :: "r"(dst), "l"(src))
#define CP_COMMIT() asm volatile("cp.async.commit_group;" ::: "memory")
#define CP_WAIT(n)  asm volatile("cp.async.wait_group %0;" :: "n"(n) : "memory")

__device__ __forceinline__ void ldsm4(uint32_t* r, uint32_t addr) {
    asm volatile("ldmatrix.sync.aligned.m8n8.x4.shared.b16 {%0,%1,%2,%3}, [%4];"
                 : "=r"(r[0]), "=r"(r[1]), "=r"(r[2]), "=r"(r[3]) : "r"(addr));
}
__device__ __forceinline__ void mma16816(float* c, const uint32_t* a, const uint32_t* b) {
    asm volatile("mma.sync.aligned.m16n8k16.row.col.f32.f16.f16.f32 "
                 "{%0,%1,%2,%3}, {%4,%5,%6,%7}, {%8,%9}, {%0,%1,%2,%3};"
                 : "+f"(c[0]), "+f"(c[1]), "+f"(c[2]), "+f"(c[3])
                 : "r"(a[0]), "r"(a[1]), "r"(a[2]), "r"(a[3]), "r"(b[0]), "r"(b[1]));
}
__device__ __forceinline__ float fast_tanh(float x) {
    float t = __expf(2.0f * x);
    return (t - 1.0f) / (t + 1.0f);
}
__device__ __forceinline__ float fast_sigmoid(float x) {
    return 1.0f / (1.0f + __expf(-x));
}

// ---------------- prep kernels ----------------
__global__ void prep_x_kernel(const float4* __restrict__ x4) {
    size_t i = (size_t)blockIdx.x * 256 + threadIdx.x;      // 8388608 threads
    float4 f = x4[i];
    __half2 h01 = __floats2half2_rn(f.x, f.y);
    __half2 h23 = __floats2half2_rn(f.z, f.w);
    size_t o = i * 4;
    __half2* dst = (__half2*)(g_x + o);
    dst[0] = h01;
    dst[1] = h23;
}

// Coalesced transpose+convert: 32x32 tiles through smem.
__global__ void prep_vu_kernel(const float* __restrict__ v, const float* __restrict__ u) {
    __shared__ float tv[32][33], tu[32][33];
    const int kt = blockIdx.x * 32;
    const int lt = blockIdx.y * 32;
    const int tx = threadIdx.x & 31;
    const int ty = threadIdx.x >> 5;    // 0..7
#pragma unroll
    for (int r = 0; r < 32; r += 8) {
        tv[ty + r][tx] = v[(size_t)(kt + ty + r) * L_DIM + lt + tx];
        tu[ty + r][tx] = u[(size_t)(kt + ty + r) * L_DIM + lt + tx];
    }
    __syncthreads();
#pragma unroll
    for (int r = 0; r < 32; r += 8) {
        int l = lt + ty + r, k = kt + tx;
        g_v[(size_t)l * IN_DIM + k] = __float2half_rn(tv[tx][ty + r]);
        g_u[(size_t)l * IN_DIM + k] = __float2half_rn(tu[tx][ty + r]);
    }
}

// ---------------- main fused GEMM kernel ----------------
// One CTA per (instance n, 64-col l-chunk). 256 threads / 8 warps, 3 CTAs/SM.
// 2-stage cp.async pipeline (CP_WAIT(0) -> sync -> issue it+1 -> compute it).
// Combined B tile: 128 rows = 64 V-rows then 64 U-rows, BK=64 columns.
// Warp tile 32 M x 64 N: mw = wid&3 (row band), nw = wid>>2 (0: V, 1: U).
// SMEM map (bytes):
#define SM_W      0          // 64 f32 = 256
#define SM_TILES  1024       // 2 stages x 32KB
#define BUF_STRIDE 32768     // per stage: A 16K (128 rows x 128B), B 16K (128 rows x 128B)
#define OFF_A     0
#define OFF_B     16384
#define SM_STASH  SM_TILES   // stash ALIASES stage buffers (used only after mainloop)
#define STASH_STRIDE 136     // 64 cols fp16 + 8B pad
#define SM_TOTAL  (SM_TILES + 2 * BUF_STRIDE)   // 66560

#define BK 64
#define NI (IN_DIM / BK)     // 16 K-iterations

__global__ void __launch_bounds__(256, 3)
mil_gemm_kernel(const float* __restrict__ w)
{
    extern __shared__ char smem[];
    const int task  = blockIdx.x;      // 0..2047
    const int n     = task >> 3;
    const int chunk = task & 7;
    const int l0    = chunk * 64;
    const int tid   = threadIdx.x;
    const int lane  = tid & 31;
    const int wid   = tid >> 5;
    const int mw    = wid & 3;    // M band: rows mw*32..+31
    const int nw    = wid >> 2;   // 0: V cols (B rows 0-63), 1: U cols (B rows 64-127)
    const uint32_t smem_base = smem_u32(smem);

    // w slice for this l-chunk into smem
    float* ws = (float*)(smem + SM_W);
    if (tid < 64) ws[tid] = w[l0 + tid];

    const __half* xp = g_x + (size_t)n * BATCH * IN_DIM;

    // ---- per-thread cp.async assignments (per stage: A 1024 + B 1024 chunks, 8/thread) ----
    const __half* srcA[4];
    uint32_t dstA[4];
#pragma unroll
    for (int j = 0; j < 4; j++) {
        int idx = j * 256 + tid;
        int row = idx >> 3;
        int seg = idx & 7;
        srcA[j] = xp + (size_t)row * IN_DIM + seg * 8;
        dstA[j] = SM_TILES + OFF_A + SWZ128(row * 128 + seg * 16);
    }
    const __half* srcB[4];
    uint32_t dstB[4];
#pragma unroll
    for (int j = 0; j < 4; j++) {
        int idx  = j * 256 + tid;
        int brow = idx >> 3;          // 0..127: 0-63 V, 64-127 U
        int seg  = idx & 7;
        const __half* mat = (brow < 64) ? g_v : g_u;
        srcB[j] = mat + (size_t)(l0 + (brow & 63)) * IN_DIM + seg * 8;
        dstB[j] = SM_TILES + OFF_B + SWZ128(brow * 128 + seg * 16);
    }

    float acc[2][8][4];
#pragma unroll
    for (int mt = 0; mt < 2; mt++)
#pragma unroll
        for (int nt = 0; nt < 8; nt++)
#pragma unroll
            for (int r = 0; r < 4; r++) acc[mt][nt][r] = 0.f;

    // ---- prologue: stage 0 ----
    {
        uint32_t bb = smem_base;
#pragma unroll
        for (int j = 0; j < 4; j++) CP16(bb + dstA[j], srcA[j]);
#pragma unroll
        for (int j = 0; j < 4; j++) CP16(bb + dstB[j], srcB[j]);
        CP_COMMIT();
    }

    for (int it = 0; it < NI; it++) {
        CP_WAIT(0);            // stage `it` complete
        __syncthreads();       // all warps done reading stage `it-1` (slot (it+1)&1)
        if (it + 1 < NI) {
            uint32_t bb = smem_base + ((it + 1) & 1) * BUF_STRIDE;
            int k0 = (it + 1) * BK;
#pragma unroll
            for (int j = 0; j < 4; j++) CP16(bb + dstA[j], srcA[j] + k0);
#pragma unroll
            for (int j = 0; j < 4; j++) CP16(bb + dstB[j], srcB[j] + k0);
            CP_COMMIT();
        }

        const uint32_t bb = smem_base + (it & 1) * BUF_STRIDE;
        const uint32_t aA = bb + SM_TILES + OFF_A;
        const uint32_t bB = bb + SM_TILES + OFF_B;

#pragma unroll
        for (int ks = 0; ks < 4; ks++) {
            // A fragments: row = mw*32 + mt*16 + (lane&15), k-half = (lane>>4)*8
            uint32_t af[2][4];
            const uint32_t akoff = ks * 32 + (lane >> 4) * 16;
#pragma unroll
            for (int mt = 0; mt < 2; mt++) {
                uint32_t rowb = (mw * 32 + mt * 16 + (lane & 15)) * 128;
                ldsm4(af[mt], aA + SWZ128(rowb + akoff));
            }
            const uint32_t bkoff = ks * 32 + ((lane >> 3) & 1) * 16;
#pragma unroll
            for (int ntp = 0; ntp < 4; ntp++) {
                uint32_t rowb = (nw * 64 + ntp * 16 + ((lane >> 4) & 1) * 8 + (lane & 7)) * 128;
                uint32_t bf[4];
                ldsm4(bf, bB + SWZ128(rowb + bkoff));
#pragma unroll
                for (int half = 0; half < 2; half++) {
                    int nt = ntp * 2 + half;
#pragma unroll
                    for (int mt = 0; mt < 2; mt++)
                        mma16816(acc[mt][nt], af[mt], bf + half * 2);
                }
            }
        }
    }
    __syncthreads();   // mainloop smem reads done; stage buffers may now be reused as stash

    // ---- epilogue ----
    if (nw == 0) {
        // V warps: stash tanh as fp16 (rows mw*32..+31, all 64 chunk cols)
#pragma unroll
        for (int mt = 0; mt < 2; mt++)
#pragma unroll
            for (int nt = 0; nt < 8; nt++) {
                int col = nt * 8 + (lane & 3) * 2;
#pragma unroll
                for (int half = 0; half < 2; half++) {
                    int row = mw * 32 + mt * 16 + half * 8 + (lane >> 2);
                    float h0 = fast_tanh(acc[mt][nt][half * 2 + 0]);
                    float h1 = fast_tanh(acc[mt][nt][half * 2 + 1]);
                    *(__half2*)(smem + SM_STASH + row * STASH_STRIDE + col * 2) =
                        __floats2half2_rn(h0, h1);
                }
            }
    }
    __syncthreads();

    if (nw == 1) {
        // U warps: gate + weight + direct partial-score write (one warp per row band)
        float rowacc[4] = {0.f, 0.f, 0.f, 0.f};
#pragma unroll
        for (int mt = 0; mt < 2; mt++)
#pragma unroll
            for (int nt = 0; nt < 8; nt++) {
                int vcol = nt * 8 + (lane & 3) * 2;
                float w0 = ws[vcol + 0];
                float w1 = ws[vcol + 1];
#pragma unroll
                for (int half = 0; half < 2; half++) {
                    int row = mw * 32 + mt * 16 + half * 8 + (lane >> 2);
                    __half2 hh = *(const __half2*)(smem + SM_STASH +
                                                   row * STASH_STRIDE + vcol * 2);
                    float g0 = fast_sigmoid(acc[mt][nt][half * 2 + 0]);
                    float g1 = fast_sigmoid(acc[mt][nt][half * 2 + 1]);
                    rowacc[mt * 2 + half] += __low2float(hh)  * g0 * w0 +
                                             __high2float(hh) * g1 * w1;
                }
            }
#pragma unroll
        for (int ri = 0; ri < 4; ri++) {
            float p = rowacc[ri];
            p += __shfl_xor_sync(0xffffffffu, p, 1);
            p += __shfl_xor_sync(0xffffffffu, p, 2);
            if ((lane & 3) == 0) {
                int row = mw * 32 + (ri >> 1) * 16 + (ri & 1) * 8 + (lane >> 2);  // batch b
                g_part[(size_t)row * (N_INST * 8) + n * 8 + chunk] = p;
            }
        }
    }
}

// ---------------- softmax over instance axis (coalesced partial reads) ----------------
__global__ void softmax_kernel(float* __restrict__ out)
{
    const int b   = blockIdx.x;    // 0..127
    const int tid = threadIdx.x;   // 0..255 == n
    __shared__ float sh[256];

    const float4* p4 = (const float4*)(g_part + (size_t)b * (N_INST * 8) + tid * 8);
    float4 a = p4[0], c = p4[1];
    float s = ((a.x + a.y) + (a.z + a.w)) + ((c.x + c.y) + (c.z + c.w));
    sh[tid] = s;
    __syncthreads();
#pragma unroll
    for (int off = 128; off > 0; off >>= 1) {
        if (tid < off) sh[tid] = fmaxf(sh[tid], sh[tid + off]);
        __syncthreads();
    }
    float m = sh[0];
    __syncthreads();
    float e = __expf(s - m);
    sh[tid] = e;
    __syncthreads();
#pragma unroll
    for (int off = 128; off > 0; off >>= 1) {
        if (tid < off) sh[tid] += sh[tid + off];
        __syncthreads();
    }
    out[(size_t)tid * BATCH + b] = e / sh[0];
}

extern "C" void kernel_launch(void* const* d_in, const int* in_sizes, int n_in,
                              void* d_out, int out_size)
{
    const float* x = (const float*)d_in[0];
    const float* v = (const float*)d_in[1];
    const float* u = (const float*)d_in[2];
    const float* w = (const float*)d_in[3];
    float* out = (float*)d_out;

    cudaFuncSetAttribute(mil_gemm_kernel,
                         cudaFuncAttributeMaxDynamicSharedMemorySize, SM_TOTAL);

    prep_x_kernel<<<32768, 256>>>((const float4*)x);
    dim3 vug(32, 16);
    prep_vu_kernel<<<vug, 256>>>(v, u);
    mil_gemm_kernel<<<2048, 256, SM_TOTAL>>>(w);
    softmax_kernel<<<BATCH, 256>>>(out);
}

// round 15
// speedup vs baseline: 1.9496x; 1.9496x over previous
#include <cuda_runtime.h>
#include <cuda_fp16.h>
#include <cstdint>
#include <math.h>

#define N_INST 256
#define BATCH  128
#define IN_DIM 1024
#define L_DIM  512

// ---------------- device scratch (allocation-free rule) ----------------
__device__ __align__(256) __half g_x[(size_t)N_INST * BATCH * IN_DIM]; // 64MB fp16
__device__ __align__(256) __half g_v[L_DIM * IN_DIM];  // [l][k] transposed, fp16
__device__ __align__(256) __half g_u[L_DIM * IN_DIM];
// transposed partials: [b][n*8 + chunk] for coalesced softmax reads
__device__ float g_part[BATCH * N_INST * 8];

// ---------------- helpers ----------------
__device__ __forceinline__ uint32_t smem_u32(const void* p) {
    uint32_t a;
    asm("{ .reg .u64 t; cvta.to.shared.u64 t, %1; cvt.u32.u64 %0, t; }" : "=r"(a) : "l"(p));
    return a;
}
// 128B-row swizzle (SW128): XOR row bits [9:7] into 16B-chunk bits [6:4]
#define SWZ128(off) ((off) ^ (((off) >> 3) & 0x70))

#define CP16(dst, src) \
    asm volatile("cp.async.cg.shared.global [%0], [%1], 16;" :: "r"(dst), "l"(src))
#define CP16_CA(dst, src) \
    asm volatile("cp.async.ca.shared.global [%0], [%1], 16;" :: "r"(dst), "l"(src))
#define CP_COMMIT() asm volatile("cp.async.commit_group;" ::: "memory")
#define CP_WAIT(n)  asm volatile("cp.async.wait_group %0;" :: "n"(n) : "memory")

__device__ __forceinline__ void ldsm4(uint32_t* r, uint32_t addr) {
    asm volatile("ldmatrix.sync.aligned.m8n8.x4.shared.b16 {%0,%1,%2,%3}, [%4];"
                 : "=r"(r[0]), "=r"(r[1]), "=r"(r[2]), "=r"(r[3]) : "r"(addr));
}
__device__ __forceinline__ void mma16816(float* c, const uint32_t* a, const uint32_t* b) {
    asm volatile("mma.sync.aligned.m16n8k16.row.col.f32.f16.f16.f32 "
                 "{%0,%1,%2,%3}, {%4,%5,%6,%7}, {%8,%9}, {%0,%1,%2,%3};"
                 : "+f"(c[0]), "+f"(c[1]), "+f"(c[2]), "+f"(c[3])
                 : "r"(a[0]), "r"(a[1]), "r"(a[2]), "r"(a[3]), "r"(b[0]), "r"(b[1]));
}
__device__ __forceinline__ float fast_tanh(float x) {
    float t = __expf(2.0f * x);
    return (t - 1.0f) / (t + 1.0f);
}
__device__ __forceinline__ float fast_sigmoid(float x) {
    return 1.0f / (1.0f + __expf(-x));
}

// ---------------- prep kernels ----------------
// 32B per thread (2x float4 in, 2x uint2 out) — fewer overhead instrs per byte.
__global__ void prep_x_kernel(const float4* __restrict__ x4) {
    size_t i = ((size_t)blockIdx.x * 256 + threadIdx.x) * 2;   // 4194304 threads
    float4 f0 = x4[i];
    float4 f1 = x4[i + 1];
    __half2 a0 = __floats2half2_rn(f0.x, f0.y);
    __half2 a1 = __floats2half2_rn(f0.z, f0.w);
    __half2 b0 = __floats2half2_rn(f1.x, f1.y);
    __half2 b1 = __floats2half2_rn(f1.z, f1.w);
    __half2* dst = (__half2*)(g_x + i * 4);
    dst[0] = a0; dst[1] = a1; dst[2] = b0; dst[3] = b1;
}

// Coalesced transpose+convert: 32x32 tiles through smem.
__global__ void prep_vu_kernel(const float* __restrict__ v, const float* __restrict__ u) {
    __shared__ float tv[32][33], tu[32][33];
    const int kt = blockIdx.x * 32;
    const int lt = blockIdx.y * 32;
    const int tx = threadIdx.x & 31;
    const int ty = threadIdx.x >> 5;    // 0..7
#pragma unroll
    for (int r = 0; r < 32; r += 8) {
        tv[ty + r][tx] = v[(size_t)(kt + ty + r) * L_DIM + lt + tx];
        tu[ty + r][tx] = u[(size_t)(kt + ty + r) * L_DIM + lt + tx];
    }
    __syncthreads();
#pragma unroll
    for (int r = 0; r < 32; r += 8) {
        int l = lt + ty + r, k = kt + tx;
        g_v[(size_t)l * IN_DIM + k] = __float2half_rn(tv[tx][ty + r]);
        g_u[(size_t)l * IN_DIM + k] = __float2half_rn(tu[tx][ty + r]);
    }
}

// ---------------- main fused GEMM kernel (R13 structure, verified best) ----------------
// One CTA per (instance n, 64-col l-chunk). 256 threads / 8 warps, 2 CTAs/SM.
// 3-stage cp.async pipeline, CP_WAIT(1). A uses .ca (co-resident CTA shares A in L1).
// Combined B tile: 128 rows = 64 V-rows then 64 U-rows, BK=64 columns.
// Warp tile 32 M x 64 N: mw = wid&3 (row band), nw = wid>>2 (0: V, 1: U).
// SMEM map (bytes):
#define SM_W      0          // 64 f32 = 256
#define SM_TILES  1024       // 3 stages x 32KB
#define BUF_STRIDE 32768     // per stage: A 16K (128 rows x 128B), B 16K (128 rows x 128B)
#define OFF_A     0
#define OFF_B     16384
#define SM_STASH  SM_TILES   // stash ALIASES stage buffers (used only after mainloop)
#define STASH_STRIDE 136     // 64 cols fp16 + 8B pad
#define SM_TOTAL  (SM_TILES + 3 * BUF_STRIDE)   // 99328

#define BK 64
#define NI (IN_DIM / BK)     // 16 K-iterations

__global__ void __launch_bounds__(256, 2)
mil_gemm_kernel(const float* __restrict__ w)
{
    extern __shared__ char smem[];
    const int task  = blockIdx.x;      // 0..2047
    const int n     = task >> 3;
    const int chunk = task & 7;
    const int l0    = chunk * 64;
    const int tid   = threadIdx.x;
    const int lane  = tid & 31;
    const int wid   = tid >> 5;
    const int mw    = wid & 3;    // M band: rows mw*32..+31
    const int nw    = wid >> 2;   // 0: V cols (B rows 0-63), 1: U cols (B rows 64-127)
    const uint32_t smem_base = smem_u32(smem);

    // w slice for this l-chunk into smem
    float* ws = (float*)(smem + SM_W);
    if (tid < 64) ws[tid] = w[l0 + tid];

    const __half* xp = g_x + (size_t)n * BATCH * IN_DIM;

    // ---- per-thread cp.async assignments (per stage: A 1024 + B 1024 chunks, 8/thread) ----
    const __half* srcA[4];
    uint32_t dstA[4];
#pragma unroll
    for (int j = 0; j < 4; j++) {
        int idx = j * 256 + tid;
        int row = idx >> 3;
        int seg = idx & 7;
        srcA[j] = xp + (size_t)row * IN_DIM + seg * 8;
        dstA[j] = SM_TILES + OFF_A + SWZ128(row * 128 + seg * 16);
    }
    const __half* srcB[4];
    uint32_t dstB[4];
#pragma unroll
    for (int j = 0; j < 4; j++) {
        int idx  = j * 256 + tid;
        int brow = idx >> 3;          // 0..127: 0-63 V, 64-127 U
        int seg  = idx & 7;
        const __half* mat = (brow < 64) ? g_v : g_u;
        srcB[j] = mat + (size_t)(l0 + (brow & 63)) * IN_DIM + seg * 8;
        dstB[j] = SM_TILES + OFF_B + SWZ128(brow * 128 + seg * 16);
    }

    float acc[2][8][4];
#pragma unroll
    for (int mt = 0; mt < 2; mt++)
#pragma unroll
        for (int nt = 0; nt < 8; nt++)
#pragma unroll
            for (int r = 0; r < 4; r++) acc[mt][nt][r] = 0.f;

    // ---- prologue: stages 0 and 1 ----
#pragma unroll
    for (int s = 0; s < 2; s++) {
        uint32_t bb = smem_base + s * BUF_STRIDE;
        int k0 = s * BK;
#pragma unroll
        for (int j = 0; j < 4; j++) CP16_CA(bb + dstA[j], srcA[j] + k0);
#pragma unroll
        for (int j = 0; j < 4; j++) CP16(bb + dstB[j], srcB[j] + k0);
        CP_COMMIT();
    }

    int slot = 0, nslot = 2;
    for (int it = 0; it < NI; it++) {
        if (it + 1 < NI) { CP_WAIT(1); } else { CP_WAIT(0); }
        __syncthreads();
        if (it + 2 < NI) {
            uint32_t bb = smem_base + nslot * BUF_STRIDE;
            int k0 = (it + 2) * BK;
#pragma unroll
            for (int j = 0; j < 4; j++) CP16_CA(bb + dstA[j], srcA[j] + k0);
#pragma unroll
            for (int j = 0; j < 4; j++) CP16(bb + dstB[j], srcB[j] + k0);
            CP_COMMIT();
            nslot = (nslot == 2) ? 0 : nslot + 1;
        }

        const uint32_t bb = smem_base + slot * BUF_STRIDE;
        slot = (slot == 2) ? 0 : slot + 1;
        const uint32_t aA = bb + SM_TILES + OFF_A;
        const uint32_t bB = bb + SM_TILES + OFF_B;

#pragma unroll
        for (int ks = 0; ks < 4; ks++) {
            // A fragments: row = mw*32 + mt*16 + (lane&15), k-half = (lane>>4)*8
            uint32_t af[2][4];
            const uint32_t akoff = ks * 32 + (lane >> 4) * 16;
#pragma unroll
            for (int mt = 0; mt < 2; mt++) {
                uint32_t rowb = (mw * 32 + mt * 16 + (lane & 15)) * 128;
                ldsm4(af[mt], aA + SWZ128(rowb + akoff));
            }
            const uint32_t bkoff = ks * 32 + ((lane >> 3) & 1) * 16;
#pragma unroll
            for (int ntp = 0; ntp < 4; ntp++) {
                uint32_t rowb = (nw * 64 + ntp * 16 + ((lane >> 4) & 1) * 8 + (lane & 7)) * 128;
                uint32_t bf[4];
                ldsm4(bf, bB + SWZ128(rowb + bkoff));
#pragma unroll
                for (int half = 0; half < 2; half++) {
                    int nt = ntp * 2 + half;
#pragma unroll
                    for (int mt = 0; mt < 2; mt++)
                        mma16816(acc[mt][nt], af[mt], bf + half * 2);
                }
            }
        }
    }
    __syncthreads();   // mainloop smem reads done; stage buffers may now be reused as stash

    // ---- epilogue ----
    if (nw == 0) {
        // V warps: stash tanh as fp16 (rows mw*32..+31, all 64 chunk cols)
#pragma unroll
        for (int mt = 0; mt < 2; mt++)
#pragma unroll
            for (int nt = 0; nt < 8; nt++) {
                int col = nt * 8 + (lane & 3) * 2;
#pragma unroll
                for (int half = 0; half < 2; half++) {
                    int row = mw * 32 + mt * 16 + half * 8 + (lane >> 2);
                    float h0 = fast_tanh(acc[mt][nt][half * 2 + 0]);
                    float h1 = fast_tanh(acc[mt][nt][half * 2 + 1]);
                    *(__half2*)(smem + SM_STASH + row * STASH_STRIDE + col * 2) =
                        __floats2half2_rn(h0, h1);
                }
            }
    }
    __syncthreads();

    if (nw == 1) {
        // U warps: gate + weight + direct partial-score write (one warp per row band)
        float rowacc[4] = {0.f, 0.f, 0.f, 0.f};
#pragma unroll
        for (int mt = 0; mt < 2; mt++)
#pragma unroll
            for (int nt = 0; nt < 8; nt++) {
                int vcol = nt * 8 + (lane & 3) * 2;
                float w0 = ws[vcol + 0];
                float w1 = ws[vcol + 1];
#pragma unroll
                for (int half = 0; half < 2; half++) {
                    int row = mw * 32 + mt * 16 + half * 8 + (lane >> 2);
                    __half2 hh = *(const __half2*)(smem + SM_STASH +
                                                   row * STASH_STRIDE + vcol * 2);
                    float g0 = fast_sigmoid(acc[mt][nt][half * 2 + 0]);
                    float g1 = fast_sigmoid(acc[mt][nt][half * 2 + 1]);
                    rowacc[mt * 2 + half] += __low2float(hh)  * g0 * w0 +
                                             __high2float(hh) * g1 * w1;
                }
            }
#pragma unroll
        for (int ri = 0; ri < 4; ri++) {
            float p = rowacc[ri];
            p += __shfl_xor_sync(0xffffffffu, p, 1);
            p += __shfl_xor_sync(0xffffffffu, p, 2);
            if ((lane & 3) == 0) {
                int row = mw * 32 + (ri >> 1) * 16 + (ri & 1) * 8 + (lane >> 2);  // batch b
                g_part[(size_t)row * (N_INST * 8) + n * 8 + chunk] = p;
            }
        }
    }
}

// ---------------- softmax over instance axis (coalesced partial reads) ----------------
__global__ void softmax_kernel(float* __restrict__ out)
{
    const int b   = blockIdx.x;    // 0..127
    const int tid = threadIdx.x;   // 0..255 == n
    __shared__ float sh[256];

    const float4* p4 = (const float4*)(g_part + (size_t)b * (N_INST * 8) + tid * 8);
    float4 a = p4[0], c = p4[1];
    float s = ((a.x + a.y) + (a.z + a.w)) + ((c.x + c.y) + (c.z + c.w));
    sh[tid] = s;
    __syncthreads();
#pragma unroll
    for (int off = 128; off > 0; off >>= 1) {
        if (tid < off) sh[tid] = fmaxf(sh[tid], sh[tid + off]);
        __syncthreads();
    }
    float m = sh[0];
    __syncthreads();
    float e = __expf(s - m);
    sh[tid] = e;
    __syncthreads();
#pragma unroll
    for (int off = 128; off > 0; off >>= 1) {
        if (tid < off) sh[tid] += sh[tid + off];
        __syncthreads();
    }
    out[(size_t)tid * BATCH + b] = e / sh[0];
}

extern "C" void kernel_launch(void* const* d_in, const int* in_sizes, int n_in,
                              void* d_out, int out_size)
{
    const float* x = (const float*)d_in[0];
    const float* v = (const float*)d_in[1];
    const float* u = (const float*)d_in[2];
    const float* w = (const float*)d_in[3];
    float* out = (float*)d_out;

    cudaFuncSetAttribute(mil_gemm_kernel,
                         cudaFuncAttributeMaxDynamicSharedMemorySize, SM_TOTAL);

    prep_x_kernel<<<16384, 256>>>((const float4*)x);
    dim3 vug(32, 16);
    prep_vu_kernel<<<vug, 256>>>(v, u);
    mil_gemm_kernel<<<2048, 256, SM_TOTAL>>>(w);
    softmax_kernel<<<BATCH, 256>>>(out);
}

// round 16
// speedup vs baseline: 2.0663x; 1.0598x over previous
#include <cuda_runtime.h>
#include <cuda_fp16.h>
#include <cstdint>
#include <math.h>

#define N_INST 256
#define BATCH  128
#define IN_DIM 1024
#define L_DIM  512

// ---------------- device scratch (allocation-free rule) ----------------
__device__ __align__(256) __half g_x[(size_t)N_INST * BATCH * IN_DIM]; // 64MB fp16
__device__ __align__(256) __half g_v[L_DIM * IN_DIM];  // [l][k] transposed, fp16
__device__ __align__(256) __half g_u[L_DIM * IN_DIM];
// transposed partials: [b][n*8 + chunk] for coalesced softmax reads
__device__ float g_part[BATCH * N_INST * 8];

// ---------------- helpers ----------------
__device__ __forceinline__ uint32_t smem_u32(const void* p) {
    uint32_t a;
    asm("{ .reg .u64 t; cvta.to.shared.u64 t, %1; cvt.u32.u64 %0, t; }" : "=r"(a) : "l"(p));
    return a;
}
// 128B-row swizzle (SW128): XOR row bits [9:7] into 16B-chunk bits [6:4]
#define SWZ128(off) ((off) ^ (((off) >> 3) & 0x70))

#define CP16(dst, src) \
    asm volatile("cp.async.cg.shared.global [%0], [%1], 16;" :: "r"(dst), "l"(src))
#define CP_COMMIT() asm volatile("cp.async.commit_group;" ::: "memory")
#define CP_WAIT(n)  asm volatile("cp.async.wait_group %0;" :: "n"(n) : "memory")

__device__ __forceinline__ void ldsm4(uint32_t* r, uint32_t addr) {
    asm volatile("ldmatrix.sync.aligned.m8n8.x4.shared.b16 {%0,%1,%2,%3}, [%4];"
                 : "=r"(r[0]), "=r"(r[1]), "=r"(r[2]), "=r"(r[3]) : "r"(addr));
}
__device__ __forceinline__ void mma16816(float* c, const uint32_t* a, const uint32_t* b) {
    asm volatile("mma.sync.aligned.m16n8k16.row.col.f32.f16.f16.f32 "
                 "{%0,%1,%2,%3}, {%4,%5,%6,%7}, {%8,%9}, {%0,%1,%2,%3};"
                 : "+f"(c[0]), "+f"(c[1]), "+f"(c[2]), "+f"(c[3])
                 : "r"(a[0]), "r"(a[1]), "r"(a[2]), "r"(a[3]), "r"(b[0]), "r"(b[1]));
}
__device__ __forceinline__ float fast_tanh(float x) {
    float t = __expf(2.0f * x);
    return (t - 1.0f) / (t + 1.0f);
}
__device__ __forceinline__ float fast_sigmoid(float x) {
    return 1.0f / (1.0f + __expf(-x));
}

// ---------------- prep kernels ----------------
// 32B per thread (2x float4 in, 2x uint2 out) — fewer overhead instrs per byte.
__global__ void prep_x_kernel(const float4* __restrict__ x4) {
    size_t i = ((size_t)blockIdx.x * 256 + threadIdx.x) * 2;   // 4194304 threads
    float4 f0 = x4[i];
    float4 f1 = x4[i + 1];
    __half2 a0 = __floats2half2_rn(f0.x, f0.y);
    __half2 a1 = __floats2half2_rn(f0.z, f0.w);
    __half2 b0 = __floats2half2_rn(f1.x, f1.y);
    __half2 b1 = __floats2half2_rn(f1.z, f1.w);
    __half2* dst = (__half2*)(g_x + i * 4);
    dst[0] = a0; dst[1] = a1; dst[2] = b0; dst[3] = b1;
}

// Coalesced transpose+convert: 32x32 tiles through smem.
__global__ void prep_vu_kernel(const float* __restrict__ v, const float* __restrict__ u) {
    __shared__ float tv[32][33], tu[32][33];
    const int kt = blockIdx.x * 32;
    const int lt = blockIdx.y * 32;
    const int tx = threadIdx.x & 31;
    const int ty = threadIdx.x >> 5;    // 0..7
#pragma unroll
    for (int r = 0; r < 32; r += 8) {
        tv[ty + r][tx] = v[(size_t)(kt + ty + r) * L_DIM + lt + tx];
        tu[ty + r][tx] = u[(size_t)(kt + ty + r) * L_DIM + lt + tx];
    }
    __syncthreads();
#pragma unroll
    for (int r = 0; r < 32; r += 8) {
        int l = lt + ty + r, k = kt + tx;
        g_v[(size_t)l * IN_DIM + k] = __float2half_rn(tv[tx][ty + r]);
        g_u[(size_t)l * IN_DIM + k] = __float2half_rn(tu[tx][ty + r]);
    }
}

// ---------------- main fused GEMM kernel (R13 structure, verified best) ----------------
// One CTA per (instance n, 64-col l-chunk). 256 threads / 8 warps, 2 CTAs/SM.
// 3-stage cp.async pipeline with CP_WAIT(1); all loads .cg (L1 has no room: 228-198=30KB).
// Combined B tile: 128 rows = 64 V-rows then 64 U-rows, BK=64 columns.
// Warp tile 32 M x 64 N: mw = wid&3 (row band), nw = wid>>2 (0: V, 1: U).
// SMEM map (bytes):
#define SM_W      0          // 64 f32 = 256
#define SM_TILES  1024       // 3 stages x 32KB
#define BUF_STRIDE 32768     // per stage: A 16K (128 rows x 128B), B 16K (128 rows x 128B)
#define OFF_A     0
#define OFF_B     16384
#define SM_STASH  SM_TILES   // stash ALIASES stage buffers (used only after mainloop)
#define STASH_STRIDE 136     // 64 cols fp16 + 8B pad
#define SM_TOTAL  (SM_TILES + 3 * BUF_STRIDE)   // 99328

#define BK 64
#define NI (IN_DIM / BK)     // 16 K-iterations

__global__ void __launch_bounds__(256, 2)
mil_gemm_kernel(const float* __restrict__ w)
{
    extern __shared__ char smem[];
    const int task  = blockIdx.x;      // 0..2047
    const int n     = task >> 3;
    const int chunk = task & 7;
    const int l0    = chunk * 64;
    const int tid   = threadIdx.x;
    const int lane  = tid & 31;
    const int wid   = tid >> 5;
    const int mw    = wid & 3;    // M band: rows mw*32..+31
    const int nw    = wid >> 2;   // 0: V cols (B rows 0-63), 1: U cols (B rows 64-127)
    const uint32_t smem_base = smem_u32(smem);

    // w slice for this l-chunk into smem
    float* ws = (float*)(smem + SM_W);
    if (tid < 64) ws[tid] = w[l0 + tid];

    const __half* xp = g_x + (size_t)n * BATCH * IN_DIM;

    // ---- per-thread cp.async assignments (per stage: A 1024 + B 1024 chunks, 8/thread) ----
    const __half* srcA[4];
    uint32_t dstA[4];
#pragma unroll
    for (int j = 0; j < 4; j++) {
        int idx = j * 256 + tid;
        int row = idx >> 3;
        int seg = idx & 7;
        srcA[j] = xp + (size_t)row * IN_DIM + seg * 8;
        dstA[j] = SM_TILES + OFF_A + SWZ128(row * 128 + seg * 16);
    }
    const __half* srcB[4];
    uint32_t dstB[4];
#pragma unroll
    for (int j = 0; j < 4; j++) {
        int idx  = j * 256 + tid;
        int brow = idx >> 3;          // 0..127: 0-63 V, 64-127 U
        int seg  = idx & 7;
        const __half* mat = (brow < 64) ? g_v : g_u;
        srcB[j] = mat + (size_t)(l0 + (brow & 63)) * IN_DIM + seg * 8;
        dstB[j] = SM_TILES + OFF_B + SWZ128(brow * 128 + seg * 16);
    }

    float acc[2][8][4];
#pragma unroll
    for (int mt = 0; mt < 2; mt++)
#pragma unroll
        for (int nt = 0; nt < 8; nt++)
#pragma unroll
            for (int r = 0; r < 4; r++) acc[mt][nt][r] = 0.f;

    // ---- prologue: stages 0 and 1 ----
#pragma unroll
    for (int s = 0; s < 2; s++) {
        uint32_t bb = smem_base + s * BUF_STRIDE;
        int k0 = s * BK;
#pragma unroll
        for (int j = 0; j < 4; j++) CP16(bb + dstA[j], srcA[j] + k0);
#pragma unroll
        for (int j = 0; j < 4; j++) CP16(bb + dstB[j], srcB[j] + k0);
        CP_COMMIT();
    }

    int slot = 0, nslot = 2;
    for (int it = 0; it < NI; it++) {
        if (it + 1 < NI) { CP_WAIT(1); } else { CP_WAIT(0); }
        __syncthreads();
        if (it + 2 < NI) {
            uint32_t bb = smem_base + nslot * BUF_STRIDE;
            int k0 = (it + 2) * BK;
#pragma unroll
            for (int j = 0; j < 4; j++) CP16(bb + dstA[j], srcA[j] + k0);
#pragma unroll
            for (int j = 0; j < 4; j++) CP16(bb + dstB[j], srcB[j] + k0);
            CP_COMMIT();
            nslot = (nslot == 2) ? 0 : nslot + 1;
        }

        const uint32_t bb = smem_base + slot * BUF_STRIDE;
        slot = (slot == 2) ? 0 : slot + 1;
        const uint32_t aA = bb + SM_TILES + OFF_A;
        const uint32_t bB = bb + SM_TILES + OFF_B;

#pragma unroll
        for (int ks = 0; ks < 4; ks++) {
            // A fragments: row = mw*32 + mt*16 + (lane&15), k-half = (lane>>4)*8
            uint32_t af[2][4];
            const uint32_t akoff = ks * 32 + (lane >> 4) * 16;
#pragma unroll
            for (int mt = 0; mt < 2; mt++) {
                uint32_t rowb = (mw * 32 + mt * 16 + (lane & 15)) * 128;
                ldsm4(af[mt], aA + SWZ128(rowb + akoff));
            }
            const uint32_t bkoff = ks * 32 + ((lane >> 3) & 1) * 16;
#pragma unroll
            for (int ntp = 0; ntp < 4; ntp++) {
                uint32_t rowb = (nw * 64 + ntp * 16 + ((lane >> 4) & 1) * 8 + (lane & 7)) * 128;
                uint32_t bf[4];
                ldsm4(bf, bB + SWZ128(rowb + bkoff));
#pragma unroll
                for (int half = 0; half < 2; half++) {
                    int nt = ntp * 2 + half;
#pragma unroll
                    for (int mt = 0; mt < 2; mt++)
                        mma16816(acc[mt][nt], af[mt], bf + half * 2);
                }
            }
        }
    }
    __syncthreads();   // mainloop smem reads done; stage buffers may now be reused as stash

    // ---- epilogue ----
    if (nw == 0) {
        // V warps: stash tanh as fp16 (rows mw*32..+31, all 64 chunk cols)
#pragma unroll
        for (int mt = 0; mt < 2; mt++)
#pragma unroll
            for (int nt = 0; nt < 8; nt++) {
                int col = nt * 8 + (lane & 3) * 2;
#pragma unroll
                for (int half = 0; half < 2; half++) {
                    int row = mw * 32 + mt * 16 + half * 8 + (lane >> 2);
                    float h0 = fast_tanh(acc[mt][nt][half * 2 + 0]);
                    float h1 = fast_tanh(acc[mt][nt][half * 2 + 1]);
                    *(__half2*)(smem + SM_STASH + row * STASH_STRIDE + col * 2) =
                        __floats2half2_rn(h0, h1);
                }
            }
    }
    __syncthreads();

    if (nw == 1) {
        // U warps: gate + weight + direct partial-score write (one warp per row band)
        float rowacc[4] = {0.f, 0.f, 0.f, 0.f};
#pragma unroll
        for (int mt = 0; mt < 2; mt++)
#pragma unroll
            for (int nt = 0; nt < 8; nt++) {
                int vcol = nt * 8 + (lane & 3) * 2;
                float w0 = ws[vcol + 0];
                float w1 = ws[vcol + 1];
#pragma unroll
                for (int half = 0; half < 2; half++) {
                    int row = mw * 32 + mt * 16 + half * 8 + (lane >> 2);
                    __half2 hh = *(const __half2*)(smem + SM_STASH +
                                                   row * STASH_STRIDE + vcol * 2);
                    float g0 = fast_sigmoid(acc[mt][nt][half * 2 + 0]);
                    float g1 = fast_sigmoid(acc[mt][nt][half * 2 + 1]);
                    rowacc[mt * 2 + half] += __low2float(hh)  * g0 * w0 +
                                             __high2float(hh) * g1 * w1;
                }
            }
#pragma unroll
        for (int ri = 0; ri < 4; ri++) {
            float p = rowacc[ri];
            p += __shfl_xor_sync(0xffffffffu, p, 1);
            p += __shfl_xor_sync(0xffffffffu, p, 2);
            if ((lane & 3) == 0) {
                int row = mw * 32 + (ri >> 1) * 16 + (ri & 1) * 8 + (lane >> 2);  // batch b
                g_part[(size_t)row * (N_INST * 8) + n * 8 + chunk] = p;
            }
        }
    }
}

// ---------------- softmax over instance axis (coalesced partial reads) ----------------
__global__ void softmax_kernel(float* __restrict__ out)
{
    const int b   = blockIdx.x;    // 0..127
    const int tid = threadIdx.x;   // 0..255 == n
    __shared__ float sh[256];

    const float4* p4 = (const float4*)(g_part + (size_t)b * (N_INST * 8) + tid * 8);
    float4 a = p4[0], c = p4[1];
    float s = ((a.x + a.y) + (a.z + a.w)) + ((c.x + c.y) + (c.z + c.w));
    sh[tid] = s;
    __syncthreads();
#pragma unroll
    for (int off = 128; off > 0; off >>= 1) {
        if (tid < off) sh[tid] = fmaxf(sh[tid], sh[tid + off]);
        __syncthreads();
    }
    float m = sh[0];
    __syncthreads();
    float e = __expf(s - m);
    sh[tid] = e;
    __syncthreads();
#pragma unroll
    for (int off = 128; off > 0; off >>= 1) {
        if (tid < off) sh[tid] += sh[tid + off];
        __syncthreads();
    }
    out[(size_t)tid * BATCH + b] = e / sh[0];
}

extern "C" void kernel_launch(void* const* d_in, const int* in_sizes, int n_in,
                              void* d_out, int out_size)
{
    const float* x = (const float*)d_in[0];
    const float* v = (const float*)d_in[1];
    const float* u = (const float*)d_in[2];
    const float* w = (const float*)d_in[3];
    float* out = (float*)d_out;

    cudaFuncSetAttribute(mil_gemm_kernel,
                         cudaFuncAttributeMaxDynamicSharedMemorySize, SM_TOTAL);

    prep_x_kernel<<<16384, 256>>>((const float4*)x);
    dim3 vug(32, 16);
    prep_vu_kernel<<<vug, 256>>>(v, u);
    mil_gemm_kernel<<<2048, 256, SM_TOTAL>>>(w);
    softmax_kernel<<<BATCH, 256>>>(out);
}

// round 17
// speedup vs baseline: 2.2707x; 1.0989x over previous
#include <cuda_runtime.h>
#include <cuda_fp16.h>
#include <cstdint>
#include <math.h>

#define N_INST 256
#define BATCH  128
#define IN_DIM 1024
#define L_DIM  512

// ---------------- device scratch (allocation-free rule) ----------------
__device__ __align__(256) __half g_x[(size_t)N_INST * BATCH * IN_DIM]; // 64MB fp16
__device__ __align__(256) __half g_v[L_DIM * IN_DIM];  // [l][k] transposed, fp16
__device__ __align__(256) __half g_u[L_DIM * IN_DIM];
// transposed partials: [b][n*8 + chunk] for coalesced softmax reads
__device__ float g_part[BATCH * N_INST * 8];

// ---------------- helpers ----------------
__device__ __forceinline__ uint32_t smem_u32(const void* p) {
    uint32_t a;
    asm("{ .reg .u64 t; cvta.to.shared.u64 t, %1; cvt.u32.u64 %0, t; }" : "=r"(a) : "l"(p));
    return a;
}
// 128B-row swizzle (SW128): XOR row bits [9:7] into 16B-chunk bits [6:4]
#define SWZ128(off) ((off) ^ (((off) >> 3) & 0x70))

#define CP16(dst, src) \
    asm volatile("cp.async.cg.shared.global [%0], [%1], 16;" :: "r"(dst), "l"(src))
#define CP_COMMIT() asm volatile("cp.async.commit_group;" ::: "memory")
#define CP_WAIT(n)  asm volatile("cp.async.wait_group %0;" :: "n"(n) : "memory")

__device__ __forceinline__ void ldsm4(uint32_t* r, uint32_t addr) {
    asm volatile("ldmatrix.sync.aligned.m8n8.x4.shared.b16 {%0,%1,%2,%3}, [%4];"
                 : "=r"(r[0]), "=r"(r[1]), "=r"(r[2]), "=r"(r[3]) : "r"(addr));
}
__device__ __forceinline__ void mma16816(float* c, const uint32_t* a, const uint32_t* b) {
    asm volatile("mma.sync.aligned.m16n8k16.row.col.f32.f16.f16.f32 "
                 "{%0,%1,%2,%3}, {%4,%5,%6,%7}, {%8,%9}, {%0,%1,%2,%3};"
                 : "+f"(c[0]), "+f"(c[1]), "+f"(c[2]), "+f"(c[3])
                 : "r"(a[0]), "r"(a[1]), "r"(a[2]), "r"(a[3]), "r"(b[0]), "r"(b[1]));
}
__device__ __forceinline__ float fast_tanh(float x) {
    float t = __expf(2.0f * x);
    return (t - 1.0f) / (t + 1.0f);
}
__device__ __forceinline__ float fast_sigmoid(float x) {
    return 1.0f / (1.0f + __expf(-x));
}

// ---------------- prep kernels ----------------
// 32B per thread (2x float4 in, 2x uint2 out).
__global__ void prep_x_kernel(const float4* __restrict__ x4) {
    size_t i = ((size_t)blockIdx.x * 256 + threadIdx.x) * 2;   // 4194304 threads
    float4 f0 = x4[i];
    float4 f1 = x4[i + 1];
    __half2 a0 = __floats2half2_rn(f0.x, f0.y);
    __half2 a1 = __floats2half2_rn(f0.z, f0.w);
    __half2 b0 = __floats2half2_rn(f1.x, f1.y);
    __half2 b1 = __floats2half2_rn(f1.z, f1.w);
    __half2* dst = (__half2*)(g_x + i * 4);
    dst[0] = a0; dst[1] = a1; dst[2] = b0; dst[3] = b1;
}

// Coalesced transpose+convert: 32x32 tiles through smem.
__global__ void prep_vu_kernel(const float* __restrict__ v, const float* __restrict__ u) {
    __shared__ float tv[32][33], tu[32][33];
    const int kt = blockIdx.x * 32;
    const int lt = blockIdx.y * 32;
    const int tx = threadIdx.x & 31;
    const int ty = threadIdx.x >> 5;    // 0..7
#pragma unroll
    for (int r = 0; r < 32; r += 8) {
        tv[ty + r][tx] = v[(size_t)(kt + ty + r) * L_DIM + lt + tx];
        tu[ty + r][tx] = u[(size_t)(kt + ty + r) * L_DIM + lt + tx];
    }
    __syncthreads();
#pragma unroll
    for (int r = 0; r < 32; r += 8) {
        int l = lt + ty + r, k = kt + tx;
        g_v[(size_t)l * IN_DIM + k] = __float2half_rn(tv[tx][ty + r]);
        g_u[(size_t)l * IN_DIM + k] = __float2half_rn(tu[tx][ty + r]);
    }
}

// ---------------- main fused GEMM kernel ----------------
// One CTA per (instance n, 64-col l-chunk). 256 threads / 8 warps, 2 CTAs/SM.
// 3-stage cp.async pipeline with CP_WAIT(1); all loads .cg.
// Combined B tile: 128 rows = 64 V-rows then 64 U-rows, BK=64 columns.
// Warp tile: rows mw*32..+31 (mw=wid&3) x cols nw*32..+31 (nw=wid>>2) of the
// 64-col chunk, with BOTH the V and U accumulators held in registers so the
// gate tanh(v)*sigmoid(u)*w happens with no smem stash round-trip.
// SMEM map (bytes):
#define SM_W      0          // 64 f32 = 256
#define SM_RED    512        // 256 f32 = 1024
#define SM_TILES  2048       // 3 stages x 32KB
#define BUF_STRIDE 32768     // per stage: A 16K (128 rows x 128B), B 16K (128 rows x 128B)
#define OFF_A     0
#define OFF_B     16384
#define SM_TOTAL  (SM_TILES + 3 * BUF_STRIDE)   // 100352

#define BK 64
#define NI (IN_DIM / BK)     // 16 K-iterations

__global__ void __launch_bounds__(256, 2)
mil_gemm_kernel(const float* __restrict__ w)
{
    extern __shared__ char smem[];
    const int task  = blockIdx.x;      // 0..2047
    const int n     = task >> 3;
    const int chunk = task & 7;
    const int l0    = chunk * 64;
    const int tid   = threadIdx.x;
    const int lane  = tid & 31;
    const int wid   = tid >> 5;
    const int mw    = wid & 3;    // M band: rows mw*32..+31
    const int nw    = wid >> 2;   // col half: cols nw*32..+31 of the 64-col chunk
    const uint32_t smem_base = smem_u32(smem);

    // w slice for this l-chunk into smem
    float* ws = (float*)(smem + SM_W);
    if (tid < 64) ws[tid] = w[l0 + tid];

    const __half* xp = g_x + (size_t)n * BATCH * IN_DIM;

    // ---- per-thread cp.async assignments (per stage: A 1024 + B 1024 chunks, 8/thread) ----
    const __half* srcA[4];
    uint32_t dstA[4];
#pragma unroll
    for (int j = 0; j < 4; j++) {
        int idx = j * 256 + tid;
        int row = idx >> 3;
        int seg = idx & 7;
        srcA[j] = xp + (size_t)row * IN_DIM + seg * 8;
        dstA[j] = SM_TILES + OFF_A + SWZ128(row * 128 + seg * 16);
    }
    const __half* srcB[4];
    uint32_t dstB[4];
#pragma unroll
    for (int j = 0; j < 4; j++) {
        int idx  = j * 256 + tid;
        int brow = idx >> 3;          // 0..127: 0-63 V, 64-127 U
        int seg  = idx & 7;
        const __half* mat = (brow < 64) ? g_v : g_u;
        srcB[j] = mat + (size_t)(l0 + (brow & 63)) * IN_DIM + seg * 8;
        dstB[j] = SM_TILES + OFF_B + SWZ128(brow * 128 + seg * 16);
    }

    float accV[2][4][4], accU[2][4][4];
#pragma unroll
    for (int mt = 0; mt < 2; mt++)
#pragma unroll
        for (int nt = 0; nt < 4; nt++)
#pragma unroll
            for (int r = 0; r < 4; r++) { accV[mt][nt][r] = 0.f; accU[mt][nt][r] = 0.f; }

    // ---- prologue: stages 0 and 1 ----
#pragma unroll
    for (int s = 0; s < 2; s++) {
        uint32_t bb = smem_base + s * BUF_STRIDE;
        int k0 = s * BK;
#pragma unroll
        for (int j = 0; j < 4; j++) CP16(bb + dstA[j], srcA[j] + k0);
#pragma unroll
        for (int j = 0; j < 4; j++) CP16(bb + dstB[j], srcB[j] + k0);
        CP_COMMIT();
    }

    int slot = 0, nslot = 2;
    for (int it = 0; it < NI; it++) {
        if (it + 1 < NI) { CP_WAIT(1); } else { CP_WAIT(0); }
        __syncthreads();
        if (it + 2 < NI) {
            uint32_t bb = smem_base + nslot * BUF_STRIDE;
            int k0 = (it + 2) * BK;
#pragma unroll
            for (int j = 0; j < 4; j++) CP16(bb + dstA[j], srcA[j] + k0);
#pragma unroll
            for (int j = 0; j < 4; j++) CP16(bb + dstB[j], srcB[j] + k0);
            CP_COMMIT();
            nslot = (nslot == 2) ? 0 : nslot + 1;
        }

        const uint32_t bb = smem_base + slot * BUF_STRIDE;
        slot = (slot == 2) ? 0 : slot + 1;
        const uint32_t aA = bb + SM_TILES + OFF_A;
        const uint32_t bB = bb + SM_TILES + OFF_B;

#pragma unroll
        for (int ks = 0; ks < 4; ks++) {
            // A fragments: row = mw*32 + mt*16 + (lane&15), k-half = (lane>>4)*8
            uint32_t af[2][4];
            const uint32_t akoff = ks * 32 + (lane >> 4) * 16;
#pragma unroll
            for (int mt = 0; mt < 2; mt++) {
                uint32_t rowb = (mw * 32 + mt * 16 + (lane & 15)) * 128;
                ldsm4(af[mt], aA + SWZ128(rowb + akoff));
            }
            const uint32_t bkoff = ks * 32 + ((lane >> 3) & 1) * 16;
            const uint32_t brlane = ((lane >> 4) & 1) * 8 + (lane & 7);
            // V rows: nw*32 + ntp*16 ; U rows: 64 + nw*32 + ntp*16
#pragma unroll
            for (int ntp = 0; ntp < 2; ntp++) {
                uint32_t rowbV = (nw * 32 + ntp * 16 + brlane) * 128;
                uint32_t bfV[4];
                ldsm4(bfV, bB + SWZ128(rowbV + bkoff));
#pragma unroll
                for (int half = 0; half < 2; half++) {
                    int nt = ntp * 2 + half;
#pragma unroll
                    for (int mt = 0; mt < 2; mt++)
                        mma16816(accV[mt][nt], af[mt], bfV + half * 2);
                }
            }
#pragma unroll
            for (int ntp = 0; ntp < 2; ntp++) {
                uint32_t rowbU = (64 + nw * 32 + ntp * 16 + brlane) * 128;
                uint32_t bfU[4];
                ldsm4(bfU, bB + SWZ128(rowbU + bkoff));
#pragma unroll
                for (int half = 0; half < 2; half++) {
                    int nt = ntp * 2 + half;
#pragma unroll
                    for (int mt = 0; mt < 2; mt++)
                        mma16816(accU[mt][nt], af[mt], bfU + half * 2);
                }
            }
        }
    }

    // ---- epilogue: gate entirely in registers ----
    float rowacc[4] = {0.f, 0.f, 0.f, 0.f};
#pragma unroll
    for (int mt = 0; mt < 2; mt++)
#pragma unroll
        for (int nt = 0; nt < 4; nt++) {
            int col = nw * 32 + nt * 8 + (lane & 3) * 2;
            float w0 = ws[col + 0];
            float w1 = ws[col + 1];
#pragma unroll
            for (int half = 0; half < 2; half++) {
                float v0 = accV[mt][nt][half * 2 + 0];
                float v1 = accV[mt][nt][half * 2 + 1];
                float u0 = accU[mt][nt][half * 2 + 0];
                float u1 = accU[mt][nt][half * 2 + 1];
                rowacc[mt * 2 + half] += fast_tanh(v0) * fast_sigmoid(u0) * w0 +
                                         fast_tanh(v1) * fast_sigmoid(u1) * w1;
            }
        }

    // reduce over the 4 lanes sharing a row (lane&3), then combine col halves
    float* red = (float*)(smem + SM_RED);
#pragma unroll
    for (int ri = 0; ri < 4; ri++) {
        float p = rowacc[ri];
        p += __shfl_xor_sync(0xffffffffu, p, 1);
        p += __shfl_xor_sync(0xffffffffu, p, 2);
        if ((lane & 3) == 0) {
            int row = mw * 32 + (ri >> 1) * 16 + (ri & 1) * 8 + (lane >> 2);  // batch b
            red[nw * 128 + row] = p;
        }
    }
    __syncthreads();
    if (tid < BATCH)
        g_part[(size_t)tid * (N_INST * 8) + n * 8 + chunk] = red[tid] + red[128 + tid];
}

// ---------------- softmax over instance axis (coalesced partial reads) ----------------
__global__ void softmax_kernel(float* __restrict__ out)
{
    const int b   = blockIdx.x;    // 0..127
    const int tid = threadIdx.x;   // 0..255 == n
    __shared__ float sh[256];

    const float4* p4 = (const float4*)(g_part + (size_t)b * (N_INST * 8) + tid * 8);
    float4 a = p4[0], c = p4[1];
    float s = ((a.x + a.y) + (a.z + a.w)) + ((c.x + c.y) + (c.z + c.w));
    sh[tid] = s;
    __syncthreads();
#pragma unroll
    for (int off = 128; off > 0; off >>= 1) {
        if (tid < off) sh[tid] = fmaxf(sh[tid], sh[tid + off]);
        __syncthreads();
    }
    float m = sh[0];
    __syncthreads();
    float e = __expf(s - m);
    sh[tid] = e;
    __syncthreads();
#pragma unroll
    for (int off = 128; off > 0; off >>= 1) {
        if (tid < off) sh[tid] += sh[tid + off];
        __syncthreads();
    }
    out[(size_t)tid * BATCH + b] = e / sh[0];
}

extern "C" void kernel_launch(void* const* d_in, const int* in_sizes, int n_in,
                              void* d_out, int out_size)
{
    const float* x = (const float*)d_in[0];
    const float* v = (const float*)d_in[1];
    const float* u = (const float*)d_in[2];
    const float* w = (const float*)d_in[3];
    float* out = (float*)d_out;

    cudaFuncSetAttribute(mil_gemm_kernel,
                         cudaFuncAttributeMaxDynamicSharedMemorySize, SM_TOTAL);

    prep_x_kernel<<<16384, 256>>>((const float4*)x);
    dim3 vug(32, 16);
    prep_vu_kernel<<<vug, 256>>>(v, u);
    mil_gemm_kernel<<<2048, 256, SM_TOTAL>>>(w);
    softmax_kernel<<<BATCH, 256>>>(out);
}